// round 1
// baseline (speedup 1.0000x reference)
#include <cuda_runtime.h>
#include <math.h>

#define Bsz  2
#define Tseq 1024
#define Emb  2048
#define NH   16
#define NG   4
#define HSZ  128
#define NL   4
#define Voc  32000
#define FFD  8192
#define NTOK (Bsz*Tseq)                 // 2048
#define QKVD ((NH+2*NG)*HSZ)            // 3072
#define EPSF 1e-5f
#define ASCALE 0.08838834764831845f     // 1/sqrt(128)

// ---------------- scratch (device globals; no allocation allowed) ----------
__device__ __align__(128) float g_x  [NTOK*Emb];
__device__ __align__(128) float g_xn [NTOK*Emb];
__device__ __align__(128) float g_qkv[NTOK*QKVD];
__device__ __align__(128) float g_y  [NTOK*Emb];
__device__ __align__(128) float g_h  [NTOK*FFD];
__device__ __align__(128) float g_s  [(size_t)Bsz*NH*Tseq*Tseq];   // attention scores

// ---------------- embedding gather ----------------
__global__ void __launch_bounds__(256) embed_kernel(const int* __restrict__ idx,
                                                    const float* __restrict__ wte) {
    int i  = blockIdx.x * 256 + threadIdx.x;       // over NTOK*Emb/4
    int bt = i >> 9;                               // Emb/4 = 512
    int e4 = i & 511;
    ((float4*)g_x)[i] = ((const float4*)wte)[(size_t)idx[bt]*512 + e4];
}

// ---------------- RMSNorm: one block per row ----------------
__global__ void __launch_bounds__(256) rmsnorm_kernel(const float* __restrict__ x,
                                                      const float* __restrict__ w,
                                                      float* __restrict__ out) {
    int row = blockIdx.x;
    int t = threadIdx.x;
    const float4* xr = (const float4*)(x + (size_t)row*Emb);
    float4 a = xr[t];
    float4 b = xr[t + 256];
    float ss = a.x*a.x + a.y*a.y + a.z*a.z + a.w*a.w
             + b.x*b.x + b.y*b.y + b.z*b.z + b.w*b.w;
#pragma unroll
    for (int o = 16; o; o >>= 1) ss += __shfl_xor_sync(0xffffffffu, ss, o);
    __shared__ float red[8];
    __shared__ float sinv;
    if ((t & 31) == 0) red[t >> 5] = ss;
    __syncthreads();
    if (t == 0) {
        float tot = red[0];
#pragma unroll
        for (int i = 1; i < 8; i++) tot += red[i];
        sinv = rsqrtf(tot * (1.0f/Emb) + EPSF);
    }
    __syncthreads();
    float inv = sinv;
    const float4* wr = (const float4*)w;
    float4 w0 = wr[t], w1 = wr[t+256];
    float4* o4 = (float4*)(out + (size_t)row*Emb);
    o4[t]     = make_float4(a.x*inv*w0.x, a.y*inv*w0.y, a.z*inv*w0.z, a.w*inv*w0.w);
    o4[t+256] = make_float4(b.x*inv*w1.x, b.y*inv*w1.y, b.z*inv*w1.z, b.w*inv*w1.w);
}

// ---------------- RoPE, in-place on q and k heads of g_qkv ----------------
__global__ void __launch_bounds__(256) rope_kernel() {
    int i    = blockIdx.x * 256 + threadIdx.x;   // NTOK*(NH+NG)*64 threads
    int d    = i & 63;
    int rest = i >> 6;
    int head = rest % (NH + NG);
    int bt   = rest / (NH + NG);
    int t    = bt & (Tseq - 1);
    size_t base = (size_t)bt*QKVD + (head < NH ? head*HSZ : NH*HSZ + (head-NH)*HSZ);
    float inv_freq = powf(10000.0f, -(float)d * (1.0f/64.0f));
    float ang = (float)t * inv_freq;
    float sn, cs;
    sincosf(ang, &sn, &cs);
    float x1 = g_qkv[base + d];
    float x2 = g_qkv[base + 64 + d];
    g_qkv[base + d]      = x1*cs - x2*sn;
    g_qkv[base + 64 + d] = x2*cs + x1*sn;
}

// ---------------- GELU (tanh approx, matches jax.nn.gelu default) ----------
__device__ __forceinline__ float gelu_f(float x) {
    return 0.5f*x*(1.0f + tanhf(0.7978845608028654f*(x + 0.044715f*x*x*x)));
}

// ---------------- generic NT GEMM: C[M,N] = A[M,K] * B[N,K]^T --------------
// BM=BN=128, BK=16, 256 threads, 8x8 microtile.
// EPI: 0 = plain, 1 = gelu, 2 = add residual (Res)
template<int EPI>
__global__ void __launch_bounds__(256) gemm_nt(const float* __restrict__ A,
                                               const float* __restrict__ B,
                                               float* __restrict__ C,
                                               const float* __restrict__ Res,
                                               int M, int N, int K) {
    __shared__ float As[16][132];
    __shared__ float Bs[16][132];
    int tid = threadIdx.x;
    int lk = tid & 15, lr = tid >> 4;
    int tx = lk, ty = lr;
    const float* Ap = A + ((size_t)blockIdx.y*128 + lr)*(size_t)K + lk;
    const float* Bp = B + ((size_t)blockIdx.x*128 + lr)*(size_t)K + lk;
    float acc[8][8];
#pragma unroll
    for (int i = 0; i < 8; i++)
#pragma unroll
        for (int j = 0; j < 8; j++) acc[i][j] = 0.f;

    for (int k0 = 0; k0 < K; k0 += 16) {
#pragma unroll
        for (int r = 0; r < 8; r++) As[lk][lr + r*16] = Ap[(size_t)(r*16)*K + k0];
#pragma unroll
        for (int r = 0; r < 8; r++) Bs[lk][lr + r*16] = Bp[(size_t)(r*16)*K + k0];
        __syncthreads();
#pragma unroll
        for (int k = 0; k < 16; k++) {
            float a[8], b[8];
            *(float4*)&a[0] = *(const float4*)&As[k][ty*4];
            *(float4*)&a[4] = *(const float4*)&As[k][64 + ty*4];
            *(float4*)&b[0] = *(const float4*)&Bs[k][tx*4];
            *(float4*)&b[4] = *(const float4*)&Bs[k][64 + tx*4];
#pragma unroll
            for (int i = 0; i < 8; i++)
#pragma unroll
                for (int j = 0; j < 8; j++)
                    acc[i][j] += a[i]*b[j];
        }
        __syncthreads();
    }
#pragma unroll
    for (int i = 0; i < 8; i++) {
        int row = blockIdx.y*128 + ((i & 4) ? 64 : 0) + ty*4 + (i & 3);
        float* cp = C + (size_t)row*N + blockIdx.x*128 + tx*4;
        float4 v0 = make_float4(acc[i][0], acc[i][1], acc[i][2], acc[i][3]);
        float4 v1 = make_float4(acc[i][4], acc[i][5], acc[i][6], acc[i][7]);
        if (EPI == 1) {
            v0.x = gelu_f(v0.x); v0.y = gelu_f(v0.y); v0.z = gelu_f(v0.z); v0.w = gelu_f(v0.w);
            v1.x = gelu_f(v1.x); v1.y = gelu_f(v1.y); v1.z = gelu_f(v1.z); v1.w = gelu_f(v1.w);
        }
        if (EPI == 2) {
            const float* rp = Res + (size_t)row*N + blockIdx.x*128 + tx*4;
            float4 r0 = *(const float4*)rp;
            float4 r1 = *(const float4*)(rp + 64);
            v0.x += r0.x; v0.y += r0.y; v0.z += r0.z; v0.w += r0.w;
            v1.x += r1.x; v1.y += r1.y; v1.z += r1.z; v1.w += r1.w;
        }
        *(float4*)cp        = v0;
        *(float4*)(cp + 64) = v1;
    }
}

// ---------------- batched scores GEMM: S = Q K^T (causal tile skip) --------
__global__ void __launch_bounds__(256) score_gemm(const float* __restrict__ qkv,
                                                  float* __restrict__ S) {
    if (blockIdx.x > blockIdx.y) return;            // fully-masked upper tiles
    int z = blockIdx.z;
    int b = z >> 4, h = z & 15, g = h >> 2;
    const float* A  = qkv + (size_t)b*Tseq*QKVD + h*HSZ;            // q rows, ld=QKVD
    const float* Bm = qkv + (size_t)b*Tseq*QKVD + NH*HSZ + g*HSZ;   // k rows, ld=QKVD
    float* C = S + (size_t)z*Tseq*Tseq;

    __shared__ float As[16][132];
    __shared__ float Bs[16][132];
    int tid = threadIdx.x;
    int lk = tid & 15, lr = tid >> 4;
    int tx = lk, ty = lr;
    const float* Ap = A  + ((size_t)blockIdx.y*128 + lr)*QKVD + lk;
    const float* Bp = Bm + ((size_t)blockIdx.x*128 + lr)*QKVD + lk;
    float acc[8][8];
#pragma unroll
    for (int i = 0; i < 8; i++)
#pragma unroll
        for (int j = 0; j < 8; j++) acc[i][j] = 0.f;

    for (int k0 = 0; k0 < HSZ; k0 += 16) {
#pragma unroll
        for (int r = 0; r < 8; r++) As[lk][lr + r*16] = Ap[(size_t)(r*16)*QKVD + k0];
#pragma unroll
        for (int r = 0; r < 8; r++) Bs[lk][lr + r*16] = Bp[(size_t)(r*16)*QKVD + k0];
        __syncthreads();
#pragma unroll
        for (int k = 0; k < 16; k++) {
            float a[8], b2[8];
            *(float4*)&a[0]  = *(const float4*)&As[k][ty*4];
            *(float4*)&a[4]  = *(const float4*)&As[k][64 + ty*4];
            *(float4*)&b2[0] = *(const float4*)&Bs[k][tx*4];
            *(float4*)&b2[4] = *(const float4*)&Bs[k][64 + tx*4];
#pragma unroll
            for (int i = 0; i < 8; i++)
#pragma unroll
                for (int j = 0; j < 8; j++)
                    acc[i][j] += a[i]*b2[j];
        }
        __syncthreads();
    }
#pragma unroll
    for (int i = 0; i < 8; i++) {
        int row = blockIdx.y*128 + ((i & 4) ? 64 : 0) + ty*4 + (i & 3);
        float* cp = C + (size_t)row*Tseq + blockIdx.x*128 + tx*4;
        *(float4*)cp        = make_float4(acc[i][0], acc[i][1], acc[i][2], acc[i][3]);
        *(float4*)(cp + 64) = make_float4(acc[i][4], acc[i][5], acc[i][6], acc[i][7]);
    }
}

// ---------------- causal softmax over score rows ----------------
__global__ void __launch_bounds__(256) softmax_kernel(float* __restrict__ S) {
    size_t z = blockIdx.x;                 // B*H*T rows
    int t = blockIdx.x & (Tseq - 1);
    int jlim4 = (((t >> 7) + 1) << 7) >> 2;   // float4 index bound of live prefix
    float4* row = (float4*)(S + z*Tseq);
    int j4 = threadIdx.x;
    int j  = j4 << 2;
    bool act = j4 < jlim4;
    float4 v = make_float4(0.f, 0.f, 0.f, 0.f);
    if (act) v = row[j4];
    float s0 = (act && j   <= t) ? v.x*ASCALE : -1e30f;
    float s1 = (act && j+1 <= t) ? v.y*ASCALE : -1e30f;
    float s2 = (act && j+2 <= t) ? v.z*ASCALE : -1e30f;
    float s3 = (act && j+3 <= t) ? v.w*ASCALE : -1e30f;
    float m = fmaxf(fmaxf(s0, s1), fmaxf(s2, s3));
#pragma unroll
    for (int o = 16; o; o >>= 1) m = fmaxf(m, __shfl_xor_sync(0xffffffffu, m, o));
    __shared__ float red[8];
    __shared__ float bm, bs;
    int tid = threadIdx.x;
    if ((tid & 31) == 0) red[tid >> 5] = m;
    __syncthreads();
    if (tid == 0) {
        float mm = red[0];
#pragma unroll
        for (int i = 1; i < 8; i++) mm = fmaxf(mm, red[i]);
        bm = mm;
    }
    __syncthreads();
    float mm = bm;
    float p0 = (j   <= t) ? __expf(s0 - mm) : 0.f;
    float p1 = (j+1 <= t) ? __expf(s1 - mm) : 0.f;
    float p2 = (j+2 <= t) ? __expf(s2 - mm) : 0.f;
    float p3 = (j+3 <= t) ? __expf(s3 - mm) : 0.f;
    float sum = p0 + p1 + p2 + p3;
#pragma unroll
    for (int o = 16; o; o >>= 1) sum += __shfl_xor_sync(0xffffffffu, sum, o);
    __syncthreads();
    if ((tid & 31) == 0) red[tid >> 5] = sum;
    __syncthreads();
    if (tid == 0) {
        float tot = red[0];
#pragma unroll
        for (int i = 1; i < 8; i++) tot += red[i];
        bs = 1.0f / tot;
    }
    __syncthreads();
    float inv = bs;
    if (act) row[j4] = make_float4(p0*inv, p1*inv, p2*inv, p3*inv);
}

// ---------------- batched AV GEMM (NN): y = P * V ----------------
__global__ void __launch_bounds__(256) av_gemm(const float* __restrict__ S,
                                               const float* __restrict__ qkv,
                                               float* __restrict__ y) {
    int z = blockIdx.z;
    int b = z >> 4, h = z & 15, g = h >> 2;
    const float* A  = S + (size_t)z*Tseq*Tseq;                             // P, ld=Tseq
    const float* Bm = qkv + (size_t)b*Tseq*QKVD + (NH+NG)*HSZ + g*HSZ;     // V rows, ld=QKVD
    float* C = y + (size_t)b*Tseq*Emb + h*HSZ;                             // ld=Emb

    __shared__ float As[16][132];
    __shared__ float Bs[16][132];
    int tid = threadIdx.x;
    int lk = tid & 15, lr = tid >> 4;
    int tx = lk, ty = lr;
    int kcol = tid & 127, krow = tid >> 7;
    const float* Ap = A + ((size_t)blockIdx.y*128 + lr)*Tseq + lk;
    int Kmax = (blockIdx.y + 1) * 128;          // causal: P[t, s>t] == 0
    float acc[8][8];
#pragma unroll
    for (int i = 0; i < 8; i++)
#pragma unroll
        for (int j = 0; j < 8; j++) acc[i][j] = 0.f;

    for (int k0 = 0; k0 < Kmax; k0 += 16) {
#pragma unroll
        for (int r = 0; r < 8; r++) As[lk][lr + r*16] = Ap[(size_t)(r*16)*Tseq + k0];
#pragma unroll
        for (int r = 0; r < 8; r++) Bs[krow + r*2][kcol] = Bm[(size_t)(k0 + krow + r*2)*QKVD + kcol];
        __syncthreads();
#pragma unroll
        for (int k = 0; k < 16; k++) {
            float a[8], b2[8];
            *(float4*)&a[0]  = *(const float4*)&As[k][ty*4];
            *(float4*)&a[4]  = *(const float4*)&As[k][64 + ty*4];
            *(float4*)&b2[0] = *(const float4*)&Bs[k][tx*4];
            *(float4*)&b2[4] = *(const float4*)&Bs[k][64 + tx*4];
#pragma unroll
            for (int i = 0; i < 8; i++)
#pragma unroll
                for (int j = 0; j < 8; j++)
                    acc[i][j] += a[i]*b2[j];
        }
        __syncthreads();
    }
#pragma unroll
    for (int i = 0; i < 8; i++) {
        int row = blockIdx.y*128 + ((i & 4) ? 64 : 0) + ty*4 + (i & 3);
        float* cp = C + (size_t)row*Emb + tx*4;
        *(float4*)cp        = make_float4(acc[i][0], acc[i][1], acc[i][2], acc[i][3]);
        *(float4*)(cp + 64) = make_float4(acc[i][4], acc[i][5], acc[i][6], acc[i][7]);
    }
}

// ---------------- host entry ----------------
extern "C" void kernel_launch(void* const* d_in, const int* in_sizes, int n_in,
                              void* d_out, int out_size) {
    const int*   idx    = (const int*)  d_in[0];
    const float* wte    = (const float*)d_in[1];
    const float* qkv_w  = (const float*)d_in[2];
    const float* attn_w = (const float*)d_in[3];
    const float* fc_w   = (const float*)d_in[4];
    const float* mlp_w  = (const float*)d_in[5];
    const float* n1_w   = (const float*)d_in[6];
    const float* n2_w   = (const float*)d_in[7];
    const float* lnf_w  = (const float*)d_in[8];
    const float* lm_w   = (const float*)d_in[9];
    float* out = (float*)d_out;
    (void)in_sizes; (void)n_in; (void)out_size;

    float *px, *pxn, *pqkv, *py, *ph, *ps;
    cudaGetSymbolAddress((void**)&px,   g_x);
    cudaGetSymbolAddress((void**)&pxn,  g_xn);
    cudaGetSymbolAddress((void**)&pqkv, g_qkv);
    cudaGetSymbolAddress((void**)&py,   g_y);
    cudaGetSymbolAddress((void**)&ph,   g_h);
    cudaGetSymbolAddress((void**)&ps,   g_s);

    embed_kernel<<<NTOK*Emb/4/256, 256>>>(idx, wte);

    for (int l = 0; l < NL; l++) {
        rmsnorm_kernel<<<NTOK, 256>>>(px, n1_w + (size_t)l*Emb, pxn);
        gemm_nt<0><<<dim3(QKVD/128, NTOK/128), 256>>>(
            pxn, qkv_w + (size_t)l*QKVD*Emb, pqkv, nullptr, NTOK, QKVD, Emb);
        rope_kernel<<<NTOK*(NH+NG)*64/256, 256>>>();
        score_gemm<<<dim3(Tseq/128, Tseq/128, Bsz*NH), 256>>>(pqkv, ps);
        softmax_kernel<<<Bsz*NH*Tseq, 256>>>(ps);
        av_gemm<<<dim3(1, Tseq/128, Bsz*NH), 256>>>(ps, pqkv, py);
        gemm_nt<2><<<dim3(Emb/128, NTOK/128), 256>>>(
            py, attn_w + (size_t)l*Emb*(NH*HSZ), px, px, NTOK, Emb, NH*HSZ);
        rmsnorm_kernel<<<NTOK, 256>>>(px, n2_w + (size_t)l*Emb, pxn);
        gemm_nt<1><<<dim3(FFD/128, NTOK/128), 256>>>(
            pxn, fc_w + (size_t)l*FFD*Emb, ph, nullptr, NTOK, FFD, Emb);
        gemm_nt<2><<<dim3(Emb/128, NTOK/128), 256>>>(
            ph, mlp_w + (size_t)l*Emb*FFD, px, px, NTOK, Emb, FFD);
    }

    rmsnorm_kernel<<<NTOK, 256>>>(px, lnf_w, pxn);
    gemm_nt<0><<<dim3(Voc/128, NTOK/128), 256>>>(
        pxn, lm_w, out, nullptr, NTOK, Voc, Emb);
}

// round 5
// speedup vs baseline: 3.0247x; 3.0247x over previous
#include <cuda_runtime.h>
#include <cuda_bf16.h>
#include <math.h>
#include <stdint.h>

#define Bsz  2
#define Tseq 1024
#define Emb  2048
#define NH   16
#define NG   4
#define HSZ  128
#define NL   4
#define Voc  32000
#define FFD  8192
#define NTOK (Bsz*Tseq)                 // 2048
#define QKVD ((NH+2*NG)*HSZ)            // 3072
#define EPSF 1e-5f
#define ASCALE 0.08838834764831845f     // 1/sqrt(128)

// ---------------- scratch (device globals; no allocation allowed) ----------
__device__ __align__(128) float g_x  [NTOK*Emb];
__device__ __align__(128) float g_xn [NTOK*Emb];
__device__ __align__(128) float g_qkv[NTOK*QKVD];
__device__ __align__(128) float g_y  [NTOK*Emb];
__device__ __align__(128) float g_h  [NTOK*FFD];
__device__ __align__(128) float g_s  [(size_t)Bsz*NH*Tseq*Tseq];   // attention scores

// ==================== helpers ====================
__device__ __forceinline__ uint32_t smem_u32(const void* p) {
    uint32_t a;
    asm("{ .reg .u64 t; cvta.to.shared.u64 t, %1; cvt.u32.u64 %0, t; }" : "=r"(a) : "l"(p));
    return a;
}
__device__ __forceinline__ void ldsm_x4(uint32_t* r, uint32_t addr) {
    asm volatile("ldmatrix.sync.aligned.m8n8.x4.shared.b16 {%0,%1,%2,%3}, [%4];"
        : "=r"(r[0]), "=r"(r[1]), "=r"(r[2]), "=r"(r[3]) : "r"(addr));
}
__device__ __forceinline__ void ldsm_x2(uint32_t* r, uint32_t addr) {
    asm volatile("ldmatrix.sync.aligned.m8n8.x2.shared.b16 {%0,%1}, [%2];"
        : "=r"(r[0]), "=r"(r[1]) : "r"(addr));
}
__device__ __forceinline__ void mma_bf16(float* d, const uint32_t* a, const uint32_t* b) {
    asm volatile(
        "mma.sync.aligned.m16n8k16.row.col.f32.bf16.bf16.f32 "
        "{%0,%1,%2,%3}, {%4,%5,%6,%7}, {%8,%9}, {%0,%1,%2,%3};"
        : "+f"(d[0]), "+f"(d[1]), "+f"(d[2]), "+f"(d[3])
        : "r"(a[0]), "r"(a[1]), "r"(a[2]), "r"(a[3]), "r"(b[0]), "r"(b[1]));
}
__device__ __forceinline__ float gelu_f(float x) {
    return 0.5f*x*(1.0f + tanhf(0.7978845608028654f*(x + 0.044715f*x*x*x)));
}
__device__ __forceinline__ void split4(float4 v, uint32_t& h01, uint32_t& h23,
                                       uint32_t& l01, uint32_t& l23) {
    __nv_bfloat16 h0 = __float2bfloat16_rn(v.x);
    __nv_bfloat16 h1 = __float2bfloat16_rn(v.y);
    __nv_bfloat16 h2 = __float2bfloat16_rn(v.z);
    __nv_bfloat16 h3 = __float2bfloat16_rn(v.w);
    __nv_bfloat16 l0 = __float2bfloat16_rn(v.x - __bfloat162float(h0));
    __nv_bfloat16 l1 = __float2bfloat16_rn(v.y - __bfloat162float(h1));
    __nv_bfloat16 l2 = __float2bfloat16_rn(v.z - __bfloat162float(h2));
    __nv_bfloat16 l3 = __float2bfloat16_rn(v.w - __bfloat162float(h3));
    h01 = ((uint32_t)__bfloat16_as_ushort(h1) << 16) | __bfloat16_as_ushort(h0);
    h23 = ((uint32_t)__bfloat16_as_ushort(h3) << 16) | __bfloat16_as_ushort(h2);
    l01 = ((uint32_t)__bfloat16_as_ushort(l1) << 16) | __bfloat16_as_ushort(l0);
    l23 = ((uint32_t)__bfloat16_as_ushort(l3) << 16) | __bfloat16_as_ushort(l2);
}

// ==================== mma.sync split-bf16 GEMM ====================
// C[M,N] = A[M,K]*B[N,K]^T near-fp32. CTA 128x128, KC=32 fp32.
// smem rows padded to 80B (stride 20 banks -> ldmatrix conflict-free).
#define SROW 80                 // bytes per smem row
#define SM_AHI 0
#define SM_ALO (128*SROW)       // 10240
#define SM_BHI (2*128*SROW)     // 20480
#define SM_BLO (3*128*SROW)     // 30720
#define SM_STAGE (4*128*SROW)   // 40960
#define SM_TOTAL (2*SM_STAGE)   // 81920

template<int EPI>   // 0 plain, 1 gelu, 2 +Res
__global__ void __launch_bounds__(256) gemm_mma(const float* __restrict__ A,
                                                const float* __restrict__ B,
                                                float* __restrict__ C,
                                                const float* __restrict__ Res,
                                                int M, int N, int K) {
    extern __shared__ char sm[];
    const uint32_t smb = smem_u32(sm);
    const int tid  = threadIdx.x;
    const int lane = tid & 31;
    const int wid  = tid >> 5;
    const int wm   = wid & 3;          // 4 warps along M
    const int wn   = wid >> 2;         // 2 warps along N
    const int bm = blockIdx.x, bn = blockIdx.y;

    const int lrow = tid >> 3;         // 0..31
    const int lc4  = tid & 7;          // 0..7 (float4 within 32 floats)
    const float* Ab = A + (size_t)bm*128*K + lc4*4;
    const float* Bb = B + (size_t)bn*128*K + lc4*4;

    float acc[2][8][4];
#pragma unroll
    for (int i = 0; i < 2; i++)
#pragma unroll
        for (int j = 0; j < 8; j++)
#pragma unroll
            for (int q = 0; q < 4; q++) acc[i][j][q] = 0.f;

    const int NC = K >> 5;

    // ---- fill stage 0 ----
    {
#pragma unroll
        for (int i = 0; i < 4; i++) {
            int row = lrow + i*32;
            float4 va = *(const float4*)(Ab + (size_t)row*K);
            float4 vb = *(const float4*)(Bb + (size_t)row*K);
            uint32_t h01,h23,l01,l23;
            int off = row*SROW + lc4*8;
            split4(va, h01,h23,l01,l23);
            *(uint2*)(sm + SM_AHI + off) = make_uint2(h01,h23);
            *(uint2*)(sm + SM_ALO + off) = make_uint2(l01,l23);
            split4(vb, h01,h23,l01,l23);
            *(uint2*)(sm + SM_BHI + off) = make_uint2(h01,h23);
            *(uint2*)(sm + SM_BLO + off) = make_uint2(l01,l23);
        }
    }
    __syncthreads();

    // ldmatrix base offsets for this thread
    const int a_r  = wm*32 + (lane & 15);
    const int a_kb = (lane >> 4) << 4;
    const int b_r  = wn*64 + (lane & 7);
    const int b_kb = ((lane >> 3) & 1) << 4;

    for (int c = 0; c < NC; ++c) {
        float4 ra[4], rb[4];
        const bool more = (c + 1 < NC);
        if (more) {
            const int k0 = (c+1) << 5;
#pragma unroll
            for (int i = 0; i < 4; i++) {
                int row = lrow + i*32;
                ra[i] = *(const float4*)(Ab + (size_t)row*K + k0);
                rb[i] = *(const float4*)(Bb + (size_t)row*K + k0);
            }
        }
        // ---- compute on stage c&1 ----
        const uint32_t sb = smb + (c & 1) * SM_STAGE;
#pragma unroll
        for (int ks = 0; ks < 2; ks++) {
            uint32_t aHi[2][4], aLo[2][4];
#pragma unroll
            for (int mt = 0; mt < 2; mt++) {
                uint32_t base = sb + (a_r + mt*16)*SROW + ks*32 + a_kb;
                ldsm_x4(aHi[mt], base + SM_AHI);
                ldsm_x4(aLo[mt], base + SM_ALO);
            }
            uint32_t bHi[8][2], bLo[8][2];
#pragma unroll
            for (int nt = 0; nt < 8; nt++) {
                uint32_t base = sb + (b_r + nt*8)*SROW + ks*32 + b_kb;
                ldsm_x2(bHi[nt], base + SM_BHI);
                ldsm_x2(bLo[nt], base + SM_BLO);
            }
#pragma unroll
            for (int mt = 0; mt < 2; mt++)
#pragma unroll
                for (int nt = 0; nt < 8; nt++) {
                    mma_bf16(acc[mt][nt], aHi[mt], bHi[nt]);
                    mma_bf16(acc[mt][nt], aHi[mt], bLo[nt]);
                    mma_bf16(acc[mt][nt], aLo[mt], bHi[nt]);
                }
        }
        // ---- store prefetched chunk into other stage ----
        if (more) {
            char* stg = sm + ((c+1) & 1) * SM_STAGE;
#pragma unroll
            for (int i = 0; i < 4; i++) {
                int row = lrow + i*32;
                int off = row*SROW + lc4*8;
                uint32_t h01,h23,l01,l23;
                split4(ra[i], h01,h23,l01,l23);
                *(uint2*)(stg + SM_AHI + off) = make_uint2(h01,h23);
                *(uint2*)(stg + SM_ALO + off) = make_uint2(l01,l23);
                split4(rb[i], h01,h23,l01,l23);
                *(uint2*)(stg + SM_BHI + off) = make_uint2(h01,h23);
                *(uint2*)(stg + SM_BLO + off) = make_uint2(l01,l23);
            }
        }
        __syncthreads();
    }

    // ---- epilogue ----
#pragma unroll
    for (int mt = 0; mt < 2; mt++) {
        int r0 = bm*128 + wm*32 + mt*16 + (lane >> 2);
#pragma unroll
        for (int nt = 0; nt < 8; nt++) {
            int col = bn*128 + wn*64 + nt*8 + (lane & 3)*2;
            float* p0 = C + (size_t)r0*N + col;
            float* p1 = p0 + (size_t)8*N;
            float2 v0 = make_float2(acc[mt][nt][0], acc[mt][nt][1]);
            float2 v1 = make_float2(acc[mt][nt][2], acc[mt][nt][3]);
            if (EPI == 1) {
                v0.x = gelu_f(v0.x); v0.y = gelu_f(v0.y);
                v1.x = gelu_f(v1.x); v1.y = gelu_f(v1.y);
            }
            if (EPI == 2) {
                const float* q0 = Res + (size_t)r0*N + col;
                const float* q1 = q0 + (size_t)8*N;
                float2 u0 = *(const float2*)q0;
                float2 u1 = *(const float2*)q1;
                v0.x += u0.x; v0.y += u0.y;
                v1.x += u1.x; v1.y += u1.y;
            }
            *(float2*)p0 = v0;
            *(float2*)p1 = v1;
        }
    }
}

// ---------------- embedding gather ----------------
__global__ void __launch_bounds__(256) embed_kernel(const int* __restrict__ idx,
                                                    const float* __restrict__ wte) {
    int i  = blockIdx.x * 256 + threadIdx.x;
    int bt = i >> 9;
    int e4 = i & 511;
    ((float4*)g_x)[i] = ((const float4*)wte)[(size_t)idx[bt]*512 + e4];
}

// ---------------- RMSNorm ----------------
__global__ void __launch_bounds__(256) rmsnorm_kernel(const float* __restrict__ x,
                                                      const float* __restrict__ w,
                                                      float* __restrict__ out) {
    int row = blockIdx.x;
    int t = threadIdx.x;
    const float4* xr = (const float4*)(x + (size_t)row*Emb);
    float4 a = xr[t];
    float4 b = xr[t + 256];
    float ss = a.x*a.x + a.y*a.y + a.z*a.z + a.w*a.w
             + b.x*b.x + b.y*b.y + b.z*b.z + b.w*b.w;
#pragma unroll
    for (int o = 16; o; o >>= 1) ss += __shfl_xor_sync(0xffffffffu, ss, o);
    __shared__ float red[8];
    __shared__ float sinv;
    if ((t & 31) == 0) red[t >> 5] = ss;
    __syncthreads();
    if (t == 0) {
        float tot = red[0];
#pragma unroll
        for (int i = 1; i < 8; i++) tot += red[i];
        sinv = rsqrtf(tot * (1.0f/Emb) + EPSF);
    }
    __syncthreads();
    float inv = sinv;
    const float4* wr = (const float4*)w;
    float4 w0 = wr[t], w1 = wr[t+256];
    float4* o4 = (float4*)(out + (size_t)row*Emb);
    o4[t]     = make_float4(a.x*inv*w0.x, a.y*inv*w0.y, a.z*inv*w0.z, a.w*inv*w0.w);
    o4[t+256] = make_float4(b.x*inv*w1.x, b.y*inv*w1.y, b.z*inv*w1.z, b.w*inv*w1.w);
}

// ---------------- RoPE ----------------
__global__ void __launch_bounds__(256) rope_kernel() {
    int i    = blockIdx.x * 256 + threadIdx.x;
    int d    = i & 63;
    int rest = i >> 6;
    int head = rest % (NH + NG);
    int bt   = rest / (NH + NG);
    int t    = bt & (Tseq - 1);
    size_t base = (size_t)bt*QKVD + (head < NH ? head*HSZ : NH*HSZ + (head-NH)*HSZ);
    float inv_freq = powf(10000.0f, -(float)d * (1.0f/64.0f));
    float ang = (float)t * inv_freq;
    float sn, cs;
    sincosf(ang, &sn, &cs);
    float x1 = g_qkv[base + d];
    float x2 = g_qkv[base + 64 + d];
    g_qkv[base + d]      = x1*cs - x2*sn;
    g_qkv[base + 64 + d] = x2*cs + x1*sn;
}

// ---------------- scores GEMM (fp32 SIMT, causal tile skip) ----------------
__global__ void __launch_bounds__(256) score_gemm(const float* __restrict__ qkv,
                                                  float* __restrict__ S) {
    if (blockIdx.x > blockIdx.y) return;
    int z = blockIdx.z;
    int b = z >> 4, h = z & 15, g = h >> 2;
    const float* A  = qkv + (size_t)b*Tseq*QKVD + h*HSZ;
    const float* Bm = qkv + (size_t)b*Tseq*QKVD + NH*HSZ + g*HSZ;
    float* C = S + (size_t)z*Tseq*Tseq;

    __shared__ float As[16][132];
    __shared__ float Bs[16][132];
    int tid = threadIdx.x;
    int lk = tid & 15, lr = tid >> 4;
    int tx = lk, ty = lr;
    const float* Ap = A  + ((size_t)blockIdx.y*128 + lr)*QKVD + lk;
    const float* Bp = Bm + ((size_t)blockIdx.x*128 + lr)*QKVD + lk;
    float acc[8][8];
#pragma unroll
    for (int i = 0; i < 8; i++)
#pragma unroll
        for (int j = 0; j < 8; j++) acc[i][j] = 0.f;

    for (int k0 = 0; k0 < HSZ; k0 += 16) {
#pragma unroll
        for (int r = 0; r < 8; r++) As[lk][lr + r*16] = Ap[(size_t)(r*16)*QKVD + k0];
#pragma unroll
        for (int r = 0; r < 8; r++) Bs[lk][lr + r*16] = Bp[(size_t)(r*16)*QKVD + k0];
        __syncthreads();
#pragma unroll
        for (int k = 0; k < 16; k++) {
            float a[8], b2[8];
            *(float4*)&a[0]  = *(const float4*)&As[k][ty*4];
            *(float4*)&a[4]  = *(const float4*)&As[k][64 + ty*4];
            *(float4*)&b2[0] = *(const float4*)&Bs[k][tx*4];
            *(float4*)&b2[4] = *(const float4*)&Bs[k][64 + tx*4];
#pragma unroll
            for (int i = 0; i < 8; i++)
#pragma unroll
                for (int j = 0; j < 8; j++)
                    acc[i][j] += a[i]*b2[j];
        }
        __syncthreads();
    }
#pragma unroll
    for (int i = 0; i < 8; i++) {
        int row = blockIdx.y*128 + ((i & 4) ? 64 : 0) + ty*4 + (i & 3);
        float* cp = C + (size_t)row*Tseq + blockIdx.x*128 + tx*4;
        *(float4*)cp        = make_float4(acc[i][0], acc[i][1], acc[i][2], acc[i][3]);
        *(float4*)(cp + 64) = make_float4(acc[i][4], acc[i][5], acc[i][6], acc[i][7]);
    }
}

// ---------------- causal softmax ----------------
__global__ void __launch_bounds__(256) softmax_kernel(float* __restrict__ S) {
    size_t z = blockIdx.x;
    int t = blockIdx.x & (Tseq - 1);
    int jlim4 = (((t >> 7) + 1) << 7) >> 2;
    float4* row = (float4*)(S + z*Tseq);
    int j4 = threadIdx.x;
    int j  = j4 << 2;
    bool act = j4 < jlim4;
    float4 v = make_float4(0.f, 0.f, 0.f, 0.f);
    if (act) v = row[j4];
    float s0 = (act && j   <= t) ? v.x*ASCALE : -1e30f;
    float s1 = (act && j+1 <= t) ? v.y*ASCALE : -1e30f;
    float s2 = (act && j+2 <= t) ? v.z*ASCALE : -1e30f;
    float s3 = (act && j+3 <= t) ? v.w*ASCALE : -1e30f;
    float m = fmaxf(fmaxf(s0, s1), fmaxf(s2, s3));
#pragma unroll
    for (int o = 16; o; o >>= 1) m = fmaxf(m, __shfl_xor_sync(0xffffffffu, m, o));
    __shared__ float red[8];
    __shared__ float bm2, bs;
    int tid = threadIdx.x;
    if ((tid & 31) == 0) red[tid >> 5] = m;
    __syncthreads();
    if (tid == 0) {
        float mm = red[0];
#pragma unroll
        for (int i = 1; i < 8; i++) mm = fmaxf(mm, red[i]);
        bm2 = mm;
    }
    __syncthreads();
    float mm = bm2;
    float p0 = (j   <= t) ? __expf(s0 - mm) : 0.f;
    float p1 = (j+1 <= t) ? __expf(s1 - mm) : 0.f;
    float p2 = (j+2 <= t) ? __expf(s2 - mm) : 0.f;
    float p3 = (j+3 <= t) ? __expf(s3 - mm) : 0.f;
    float sum = p0 + p1 + p2 + p3;
#pragma unroll
    for (int o = 16; o; o >>= 1) sum += __shfl_xor_sync(0xffffffffu, sum, o);
    __syncthreads();
    if ((tid & 31) == 0) red[tid >> 5] = sum;
    __syncthreads();
    if (tid == 0) {
        float tot = red[0];
#pragma unroll
        for (int i = 1; i < 8; i++) tot += red[i];
        bs = 1.0f / tot;
    }
    __syncthreads();
    float inv = bs;
    if (act) row[j4] = make_float4(p0*inv, p1*inv, p2*inv, p3*inv);
}

// ---------------- AV GEMM (fp32 SIMT, causal K bound) ----------------
__global__ void __launch_bounds__(256) av_gemm(const float* __restrict__ S,
                                               const float* __restrict__ qkv,
                                               float* __restrict__ y) {
    int z = blockIdx.z;
    int b = z >> 4, h = z & 15, g = h >> 2;
    const float* A  = S + (size_t)z*Tseq*Tseq;
    const float* Bm = qkv + (size_t)b*Tseq*QKVD + (NH+NG)*HSZ + g*HSZ;
    float* C = y + (size_t)b*Tseq*Emb + h*HSZ;

    __shared__ float As[16][132];
    __shared__ float Bs[16][132];
    int tid = threadIdx.x;
    int lk = tid & 15, lr = tid >> 4;
    int tx = lk, ty = lr;
    int kcol = tid & 127, krow = tid >> 7;
    const float* Ap = A + ((size_t)blockIdx.y*128 + lr)*Tseq + lk;
    int Kmax = (blockIdx.y + 1) * 128;
    float acc[8][8];
#pragma unroll
    for (int i = 0; i < 8; i++)
#pragma unroll
        for (int j = 0; j < 8; j++) acc[i][j] = 0.f;

    for (int k0 = 0; k0 < Kmax; k0 += 16) {
#pragma unroll
        for (int r = 0; r < 8; r++) As[lk][lr + r*16] = Ap[(size_t)(r*16)*Tseq + k0];
#pragma unroll
        for (int r = 0; r < 8; r++) Bs[krow + r*2][kcol] = Bm[(size_t)(k0 + krow + r*2)*QKVD + kcol];
        __syncthreads();
#pragma unroll
        for (int k = 0; k < 16; k++) {
            float a[8], b2[8];
            *(float4*)&a[0]  = *(const float4*)&As[k][ty*4];
            *(float4*)&a[4]  = *(const float4*)&As[k][64 + ty*4];
            *(float4*)&b2[0] = *(const float4*)&Bs[k][tx*4];
            *(float4*)&b2[4] = *(const float4*)&Bs[k][64 + tx*4];
#pragma unroll
            for (int i = 0; i < 8; i++)
#pragma unroll
                for (int j = 0; j < 8; j++)
                    acc[i][j] += a[i]*b2[j];
        }
        __syncthreads();
    }
#pragma unroll
    for (int i = 0; i < 8; i++) {
        int row = blockIdx.y*128 + ((i & 4) ? 64 : 0) + ty*4 + (i & 3);
        float* cp = C + (size_t)row*Emb + tx*4;
        *(float4*)cp        = make_float4(acc[i][0], acc[i][1], acc[i][2], acc[i][3]);
        *(float4*)(cp + 64) = make_float4(acc[i][4], acc[i][5], acc[i][6], acc[i][7]);
    }
}

// ---------------- host entry ----------------
extern "C" void kernel_launch(void* const* d_in, const int* in_sizes, int n_in,
                              void* d_out, int out_size) {
    const int*   idx    = (const int*)  d_in[0];
    const float* wte    = (const float*)d_in[1];
    const float* qkv_w  = (const float*)d_in[2];
    const float* attn_w = (const float*)d_in[3];
    const float* fc_w   = (const float*)d_in[4];
    const float* mlp_w  = (const float*)d_in[5];
    const float* n1_w   = (const float*)d_in[6];
    const float* n2_w   = (const float*)d_in[7];
    const float* lnf_w  = (const float*)d_in[8];
    const float* lm_w   = (const float*)d_in[9];
    float* out = (float*)d_out;
    (void)in_sizes; (void)n_in; (void)out_size;

    float *px, *pxn, *pqkv, *py, *ph, *ps;
    cudaGetSymbolAddress((void**)&px,   g_x);
    cudaGetSymbolAddress((void**)&pxn,  g_xn);
    cudaGetSymbolAddress((void**)&pqkv, g_qkv);
    cudaGetSymbolAddress((void**)&py,   g_y);
    cudaGetSymbolAddress((void**)&ph,   g_h);
    cudaGetSymbolAddress((void**)&ps,   g_s);

    cudaFuncSetAttribute(gemm_mma<0>, cudaFuncAttributeMaxDynamicSharedMemorySize, SM_TOTAL);
    cudaFuncSetAttribute(gemm_mma<1>, cudaFuncAttributeMaxDynamicSharedMemorySize, SM_TOTAL);
    cudaFuncSetAttribute(gemm_mma<2>, cudaFuncAttributeMaxDynamicSharedMemorySize, SM_TOTAL);

    embed_kernel<<<NTOK*Emb/4/256, 256>>>(idx, wte);

    for (int l = 0; l < NL; l++) {
        rmsnorm_kernel<<<NTOK, 256>>>(px, n1_w + (size_t)l*Emb, pxn);
        gemm_mma<0><<<dim3(NTOK/128, QKVD/128), 256, SM_TOTAL>>>(
            pxn, qkv_w + (size_t)l*QKVD*Emb, pqkv, nullptr, NTOK, QKVD, Emb);
        rope_kernel<<<NTOK*(NH+NG)*64/256, 256>>>();
        score_gemm<<<dim3(Tseq/128, Tseq/128, Bsz*NH), 256>>>(pqkv, ps);
        softmax_kernel<<<Bsz*NH*Tseq, 256>>>(ps);
        av_gemm<<<dim3(1, Tseq/128, Bsz*NH), 256>>>(ps, pqkv, py);
        gemm_mma<2><<<dim3(NTOK/128, Emb/128), 256, SM_TOTAL>>>(
            py, attn_w + (size_t)l*Emb*(NH*HSZ), px, px, NTOK, Emb, NH*HSZ);
        rmsnorm_kernel<<<NTOK, 256>>>(px, n2_w + (size_t)l*Emb, pxn);
        gemm_mma<1><<<dim3(NTOK/128, FFD/128), 256, SM_TOTAL>>>(
            pxn, fc_w + (size_t)l*FFD*Emb, ph, nullptr, NTOK, FFD, Emb);
        gemm_mma<2><<<dim3(NTOK/128, Emb/128), 256, SM_TOTAL>>>(
            ph, mlp_w + (size_t)l*Emb*FFD, px, px, NTOK, Emb, FFD);
    }

    rmsnorm_kernel<<<NTOK, 256>>>(px, lnf_w, pxn);
    gemm_mma<0><<<dim3(NTOK/128, Voc/128), 256, SM_TOTAL>>>(
        pxn, lm_w, out, nullptr, NTOK, Voc, Emb);
}

// round 6
// speedup vs baseline: 3.7821x; 1.2504x over previous
#include <cuda_runtime.h>
#include <cuda_fp16.h>
#include <math.h>
#include <stdint.h>

#define Bsz  2
#define Tseq 1024
#define Emb  2048
#define NH   16
#define NG   4
#define HSZ  128
#define NL   4
#define Voc  32000
#define FFD  8192
#define NTOK (Bsz*Tseq)                 // 2048
#define QKVD ((NH+2*NG)*HSZ)            // 3072
#define EPSF 1e-5f
#define ASCALE 0.08838834764831845f     // 1/sqrt(128)

// ---------------- scratch (device globals; no allocation allowed) ----------
__device__ __align__(128) float g_x  [NTOK*Emb];
__device__ __align__(128) float g_xn [NTOK*Emb];
__device__ __align__(128) float g_qkv[NTOK*QKVD];
__device__ __align__(128) float g_y  [NTOK*Emb];
__device__ __align__(128) float g_h  [NTOK*FFD];
__device__ __align__(128) float g_s  [(size_t)Bsz*NH*Tseq*Tseq];   // attention scores

// ==================== helpers ====================
__device__ __forceinline__ uint32_t smem_u32(const void* p) {
    uint32_t a;
    asm("{ .reg .u64 t; cvta.to.shared.u64 t, %1; cvt.u32.u64 %0, t; }" : "=r"(a) : "l"(p));
    return a;
}
__device__ __forceinline__ void ldsm_x4(uint32_t* r, uint32_t addr) {
    asm volatile("ldmatrix.sync.aligned.m8n8.x4.shared.b16 {%0,%1,%2,%3}, [%4];"
        : "=r"(r[0]), "=r"(r[1]), "=r"(r[2]), "=r"(r[3]) : "r"(addr));
}
__device__ __forceinline__ void ldsm_x2(uint32_t* r, uint32_t addr) {
    asm volatile("ldmatrix.sync.aligned.m8n8.x2.shared.b16 {%0,%1}, [%2];"
        : "=r"(r[0]), "=r"(r[1]) : "r"(addr));
}
__device__ __forceinline__ void mma_f16(float* d, const uint32_t* a, const uint32_t* b) {
    asm volatile(
        "mma.sync.aligned.m16n8k16.row.col.f32.f16.f16.f32 "
        "{%0,%1,%2,%3}, {%4,%5,%6,%7}, {%8,%9}, {%0,%1,%2,%3};"
        : "+f"(d[0]), "+f"(d[1]), "+f"(d[2]), "+f"(d[3])
        : "r"(a[0]), "r"(a[1]), "r"(a[2]), "r"(a[3]), "r"(b[0]), "r"(b[1]));
}
__device__ __forceinline__ float gelu_f(float x) {
    return 0.5f*x*(1.0f + tanhf(0.7978845608028654f*(x + 0.044715f*x*x*x)));
}
// A: split into fp16 hi + fp16 lo (residual)
__device__ __forceinline__ void splitA4(float4 v, uint32_t& h01, uint32_t& h23,
                                        uint32_t& l01, uint32_t& l23) {
    __half h0 = __float2half_rn(v.x);
    __half h1 = __float2half_rn(v.y);
    __half h2 = __float2half_rn(v.z);
    __half h3 = __float2half_rn(v.w);
    __half l0 = __float2half_rn(v.x - __half2float(h0));
    __half l1 = __float2half_rn(v.y - __half2float(h1));
    __half l2 = __float2half_rn(v.z - __half2float(h2));
    __half l3 = __float2half_rn(v.w - __half2float(h3));
    h01 = ((uint32_t)__half_as_ushort(h1) << 16) | __half_as_ushort(h0);
    h23 = ((uint32_t)__half_as_ushort(h3) << 16) | __half_as_ushort(h2);
    l01 = ((uint32_t)__half_as_ushort(l1) << 16) | __half_as_ushort(l0);
    l23 = ((uint32_t)__half_as_ushort(l3) << 16) | __half_as_ushort(l2);
}
// B: single fp16 rounding
__device__ __forceinline__ void cvtB4(float4 v, uint32_t& h01, uint32_t& h23) {
    __half h0 = __float2half_rn(v.x);
    __half h1 = __float2half_rn(v.y);
    __half h2 = __float2half_rn(v.z);
    __half h3 = __float2half_rn(v.w);
    h01 = ((uint32_t)__half_as_ushort(h1) << 16) | __half_as_ushort(h0);
    h23 = ((uint32_t)__half_as_ushort(h3) << 16) | __half_as_ushort(h2);
}

// ==================== mma.sync 2-pass fp16 GEMM ====================
// C[M,N] = A[M,K]*B[N,K]^T.  A exact (fp16 hi+lo), B fp16-rounded.
// CTA 128x128, KC=32 fp32, smem rows 80B (conflict-free ldmatrix).
#define SROW 80
#define SM_AHI 0
#define SM_ALO (128*SROW)       // 10240
#define SM_BHI (2*128*SROW)     // 20480
#define SM_STAGE (3*128*SROW)   // 30720
#define SM_TOTAL (2*SM_STAGE)   // 61440

template<int EPI>   // 0 plain, 1 gelu, 2 +Res
__global__ void __launch_bounds__(256) gemm_mma(const float* __restrict__ A,
                                                const float* __restrict__ B,
                                                float* __restrict__ C,
                                                const float* __restrict__ Res,
                                                int M, int N, int K) {
    extern __shared__ char sm[];
    const uint32_t smb = smem_u32(sm);
    const int tid  = threadIdx.x;
    const int lane = tid & 31;
    const int wid  = tid >> 5;
    const int wm   = wid & 3;          // 4 warps along M
    const int wn   = wid >> 2;         // 2 warps along N
    const int bm = blockIdx.x, bn = blockIdx.y;

    const int lrow = tid >> 3;         // 0..31
    const int lc4  = tid & 7;          // 0..7
    const float* Ab = A + (size_t)bm*128*K + lc4*4;
    const float* Bb = B + (size_t)bn*128*K + lc4*4;

    float acc[2][8][4];
#pragma unroll
    for (int i = 0; i < 2; i++)
#pragma unroll
        for (int j = 0; j < 8; j++)
#pragma unroll
            for (int q = 0; q < 4; q++) acc[i][j][q] = 0.f;

    const int NC = K >> 5;

    // ---- fill stage 0 ----
    {
#pragma unroll
        for (int i = 0; i < 4; i++) {
            int row = lrow + i*32;
            float4 va = *(const float4*)(Ab + (size_t)row*K);
            float4 vb = *(const float4*)(Bb + (size_t)row*K);
            int off = row*SROW + lc4*8;
            uint32_t h01,h23,l01,l23;
            splitA4(va, h01,h23,l01,l23);
            *(uint2*)(sm + SM_AHI + off) = make_uint2(h01,h23);
            *(uint2*)(sm + SM_ALO + off) = make_uint2(l01,l23);
            cvtB4(vb, h01,h23);
            *(uint2*)(sm + SM_BHI + off) = make_uint2(h01,h23);
        }
    }
    __syncthreads();

    const int a_r  = wm*32 + (lane & 15);
    const int a_kb = (lane >> 4) << 4;
    const int b_r  = wn*64 + (lane & 7);
    const int b_kb = ((lane >> 3) & 1) << 4;

    for (int c = 0; c < NC; ++c) {
        float4 ra[4], rb[4];
        const bool more = (c + 1 < NC);
        if (more) {
            const int k0 = (c+1) << 5;
#pragma unroll
            for (int i = 0; i < 4; i++) {
                int row = lrow + i*32;
                ra[i] = *(const float4*)(Ab + (size_t)row*K + k0);
                rb[i] = *(const float4*)(Bb + (size_t)row*K + k0);
            }
        }
        // ---- compute on stage c&1 ----
        const uint32_t sb = smb + (c & 1) * SM_STAGE;
#pragma unroll
        for (int ks = 0; ks < 2; ks++) {
            uint32_t aHi[2][4], aLo[2][4];
#pragma unroll
            for (int mt = 0; mt < 2; mt++) {
                uint32_t base = sb + (a_r + mt*16)*SROW + ks*32 + a_kb;
                ldsm_x4(aHi[mt], base + SM_AHI);
                ldsm_x4(aLo[mt], base + SM_ALO);
            }
            uint32_t bHi[8][2];
#pragma unroll
            for (int nt = 0; nt < 8; nt++) {
                uint32_t base = sb + (b_r + nt*8)*SROW + ks*32 + b_kb;
                ldsm_x2(bHi[nt], base + SM_BHI);
            }
#pragma unroll
            for (int mt = 0; mt < 2; mt++)
#pragma unroll
                for (int nt = 0; nt < 8; nt++) {
                    mma_f16(acc[mt][nt], aHi[mt], bHi[nt]);
                    mma_f16(acc[mt][nt], aLo[mt], bHi[nt]);
                }
        }
        // ---- store prefetched chunk into other stage ----
        if (more) {
            char* stg = sm + ((c+1) & 1) * SM_STAGE;
#pragma unroll
            for (int i = 0; i < 4; i++) {
                int row = lrow + i*32;
                int off = row*SROW + lc4*8;
                uint32_t h01,h23,l01,l23;
                splitA4(ra[i], h01,h23,l01,l23);
                *(uint2*)(stg + SM_AHI + off) = make_uint2(h01,h23);
                *(uint2*)(stg + SM_ALO + off) = make_uint2(l01,l23);
                cvtB4(rb[i], h01,h23);
                *(uint2*)(stg + SM_BHI + off) = make_uint2(h01,h23);
            }
        }
        __syncthreads();
    }

    // ---- epilogue ----
#pragma unroll
    for (int mt = 0; mt < 2; mt++) {
        int r0 = bm*128 + wm*32 + mt*16 + (lane >> 2);
#pragma unroll
        for (int nt = 0; nt < 8; nt++) {
            int col = bn*128 + wn*64 + nt*8 + (lane & 3)*2;
            float* p0 = C + (size_t)r0*N + col;
            float* p1 = p0 + (size_t)8*N;
            float2 v0 = make_float2(acc[mt][nt][0], acc[mt][nt][1]);
            float2 v1 = make_float2(acc[mt][nt][2], acc[mt][nt][3]);
            if (EPI == 1) {
                v0.x = gelu_f(v0.x); v0.y = gelu_f(v0.y);
                v1.x = gelu_f(v1.x); v1.y = gelu_f(v1.y);
            }
            if (EPI == 2) {
                const float* q0 = Res + (size_t)r0*N + col;
                const float* q1 = q0 + (size_t)8*N;
                float2 u0 = *(const float2*)q0;
                float2 u1 = *(const float2*)q1;
                v0.x += u0.x; v0.y += u0.y;
                v1.x += u1.x; v1.y += u1.y;
            }
            *(float2*)p0 = v0;
            *(float2*)p1 = v1;
        }
    }
}

// ---------------- embedding gather ----------------
__global__ void __launch_bounds__(256) embed_kernel(const int* __restrict__ idx,
                                                    const float* __restrict__ wte) {
    int i  = blockIdx.x * 256 + threadIdx.x;
    int bt = i >> 9;
    int e4 = i & 511;
    ((float4*)g_x)[i] = ((const float4*)wte)[(size_t)idx[bt]*512 + e4];
}

// ---------------- RMSNorm ----------------
__global__ void __launch_bounds__(256) rmsnorm_kernel(const float* __restrict__ x,
                                                      const float* __restrict__ w,
                                                      float* __restrict__ out) {
    int row = blockIdx.x;
    int t = threadIdx.x;
    const float4* xr = (const float4*)(x + (size_t)row*Emb);
    float4 a = xr[t];
    float4 b = xr[t + 256];
    float ss = a.x*a.x + a.y*a.y + a.z*a.z + a.w*a.w
             + b.x*b.x + b.y*b.y + b.z*b.z + b.w*b.w;
#pragma unroll
    for (int o = 16; o; o >>= 1) ss += __shfl_xor_sync(0xffffffffu, ss, o);
    __shared__ float red[8];
    __shared__ float sinv;
    if ((t & 31) == 0) red[t >> 5] = ss;
    __syncthreads();
    if (t == 0) {
        float tot = red[0];
#pragma unroll
        for (int i = 1; i < 8; i++) tot += red[i];
        sinv = rsqrtf(tot * (1.0f/Emb) + EPSF);
    }
    __syncthreads();
    float inv = sinv;
    const float4* wr = (const float4*)w;
    float4 w0 = wr[t], w1 = wr[t+256];
    float4* o4 = (float4*)(out + (size_t)row*Emb);
    o4[t]     = make_float4(a.x*inv*w0.x, a.y*inv*w0.y, a.z*inv*w0.z, a.w*inv*w0.w);
    o4[t+256] = make_float4(b.x*inv*w1.x, b.y*inv*w1.y, b.z*inv*w1.z, b.w*inv*w1.w);
}

// ---------------- RoPE ----------------
__global__ void __launch_bounds__(256) rope_kernel() {
    int i    = blockIdx.x * 256 + threadIdx.x;
    int d    = i & 63;
    int rest = i >> 6;
    int head = rest % (NH + NG);
    int bt   = rest / (NH + NG);
    int t    = bt & (Tseq - 1);
    size_t base = (size_t)bt*QKVD + (head < NH ? head*HSZ : NH*HSZ + (head-NH)*HSZ);
    float inv_freq = powf(10000.0f, -(float)d * (1.0f/64.0f));
    float ang = (float)t * inv_freq;
    float sn, cs;
    sincosf(ang, &sn, &cs);
    float x1 = g_qkv[base + d];
    float x2 = g_qkv[base + 64 + d];
    g_qkv[base + d]      = x1*cs - x2*sn;
    g_qkv[base + 64 + d] = x2*cs + x1*sn;
}

// ---------------- scores GEMM (fp32 SIMT, causal tile skip) ----------------
__global__ void __launch_bounds__(256) score_gemm(const float* __restrict__ qkv,
                                                  float* __restrict__ S) {
    if (blockIdx.x > blockIdx.y) return;
    int z = blockIdx.z;
    int b = z >> 4, h = z & 15, g = h >> 2;
    const float* A  = qkv + (size_t)b*Tseq*QKVD + h*HSZ;
    const float* Bm = qkv + (size_t)b*Tseq*QKVD + NH*HSZ + g*HSZ;
    float* C = S + (size_t)z*Tseq*Tseq;

    __shared__ float As[16][132];
    __shared__ float Bs[16][132];
    int tid = threadIdx.x;
    int lk = tid & 15, lr = tid >> 4;
    int tx = lk, ty = lr;
    const float* Ap = A  + ((size_t)blockIdx.y*128 + lr)*QKVD + lk;
    const float* Bp = Bm + ((size_t)blockIdx.x*128 + lr)*QKVD + lk;
    float acc[8][8];
#pragma unroll
    for (int i = 0; i < 8; i++)
#pragma unroll
        for (int j = 0; j < 8; j++) acc[i][j] = 0.f;

    for (int k0 = 0; k0 < HSZ; k0 += 16) {
#pragma unroll
        for (int r = 0; r < 8; r++) As[lk][lr + r*16] = Ap[(size_t)(r*16)*QKVD + k0];
#pragma unroll
        for (int r = 0; r < 8; r++) Bs[lk][lr + r*16] = Bp[(size_t)(r*16)*QKVD + k0];
        __syncthreads();
#pragma unroll
        for (int k = 0; k < 16; k++) {
            float a[8], b2[8];
            *(float4*)&a[0]  = *(const float4*)&As[k][ty*4];
            *(float4*)&a[4]  = *(const float4*)&As[k][64 + ty*4];
            *(float4*)&b2[0] = *(const float4*)&Bs[k][tx*4];
            *(float4*)&b2[4] = *(const float4*)&Bs[k][64 + tx*4];
#pragma unroll
            for (int i = 0; i < 8; i++)
#pragma unroll
                for (int j = 0; j < 8; j++)
                    acc[i][j] += a[i]*b2[j];
        }
        __syncthreads();
    }
#pragma unroll
    for (int i = 0; i < 8; i++) {
        int row = blockIdx.y*128 + ((i & 4) ? 64 : 0) + ty*4 + (i & 3);
        float* cp = C + (size_t)row*Tseq + blockIdx.x*128 + tx*4;
        *(float4*)cp        = make_float4(acc[i][0], acc[i][1], acc[i][2], acc[i][3]);
        *(float4*)(cp + 64) = make_float4(acc[i][4], acc[i][5], acc[i][6], acc[i][7]);
    }
}

// ---------------- causal softmax ----------------
__global__ void __launch_bounds__(256) softmax_kernel(float* __restrict__ S) {
    size_t z = blockIdx.x;
    int t = blockIdx.x & (Tseq - 1);
    int jlim4 = (((t >> 7) + 1) << 7) >> 2;
    float4* row = (float4*)(S + z*Tseq);
    int j4 = threadIdx.x;
    int j  = j4 << 2;
    bool act = j4 < jlim4;
    float4 v = make_float4(0.f, 0.f, 0.f, 0.f);
    if (act) v = row[j4];
    float s0 = (act && j   <= t) ? v.x*ASCALE : -1e30f;
    float s1 = (act && j+1 <= t) ? v.y*ASCALE : -1e30f;
    float s2 = (act && j+2 <= t) ? v.z*ASCALE : -1e30f;
    float s3 = (act && j+3 <= t) ? v.w*ASCALE : -1e30f;
    float m = fmaxf(fmaxf(s0, s1), fmaxf(s2, s3));
#pragma unroll
    for (int o = 16; o; o >>= 1) m = fmaxf(m, __shfl_xor_sync(0xffffffffu, m, o));
    __shared__ float red[8];
    __shared__ float bm2, bs;
    int tid = threadIdx.x;
    if ((tid & 31) == 0) red[tid >> 5] = m;
    __syncthreads();
    if (tid == 0) {
        float mm = red[0];
#pragma unroll
        for (int i = 1; i < 8; i++) mm = fmaxf(mm, red[i]);
        bm2 = mm;
    }
    __syncthreads();
    float mm = bm2;
    float p0 = (j   <= t) ? __expf(s0 - mm) : 0.f;
    float p1 = (j+1 <= t) ? __expf(s1 - mm) : 0.f;
    float p2 = (j+2 <= t) ? __expf(s2 - mm) : 0.f;
    float p3 = (j+3 <= t) ? __expf(s3 - mm) : 0.f;
    float sum = p0 + p1 + p2 + p3;
#pragma unroll
    for (int o = 16; o; o >>= 1) sum += __shfl_xor_sync(0xffffffffu, sum, o);
    __syncthreads();
    if ((tid & 31) == 0) red[tid >> 5] = sum;
    __syncthreads();
    if (tid == 0) {
        float tot = red[0];
#pragma unroll
        for (int i = 1; i < 8; i++) tot += red[i];
        bs = 1.0f / tot;
    }
    __syncthreads();
    float inv = bs;
    if (act) row[j4] = make_float4(p0*inv, p1*inv, p2*inv, p3*inv);
}

// ---------------- AV GEMM (fp32 SIMT, causal K bound) ----------------
__global__ void __launch_bounds__(256) av_gemm(const float* __restrict__ S,
                                               const float* __restrict__ qkv,
                                               float* __restrict__ y) {
    int z = blockIdx.z;
    int b = z >> 4, h = z & 15, g = h >> 2;
    const float* A  = S + (size_t)z*Tseq*Tseq;
    const float* Bm = qkv + (size_t)b*Tseq*QKVD + (NH+NG)*HSZ + g*HSZ;
    float* C = y + (size_t)b*Tseq*Emb + h*HSZ;

    __shared__ float As[16][132];
    __shared__ float Bs[16][132];
    int tid = threadIdx.x;
    int lk = tid & 15, lr = tid >> 4;
    int tx = lk, ty = lr;
    int kcol = tid & 127, krow = tid >> 7;
    const float* Ap = A + ((size_t)blockIdx.y*128 + lr)*Tseq + lk;
    int Kmax = (blockIdx.y + 1) * 128;
    float acc[8][8];
#pragma unroll
    for (int i = 0; i < 8; i++)
#pragma unroll
        for (int j = 0; j < 8; j++) acc[i][j] = 0.f;

    for (int k0 = 0; k0 < Kmax; k0 += 16) {
#pragma unroll
        for (int r = 0; r < 8; r++) As[lk][lr + r*16] = Ap[(size_t)(r*16)*Tseq + k0];
#pragma unroll
        for (int r = 0; r < 8; r++) Bs[krow + r*2][kcol] = Bm[(size_t)(k0 + krow + r*2)*QKVD + kcol];
        __syncthreads();
#pragma unroll
        for (int k = 0; k < 16; k++) {
            float a[8], b2[8];
            *(float4*)&a[0]  = *(const float4*)&As[k][ty*4];
            *(float4*)&a[4]  = *(const float4*)&As[k][64 + ty*4];
            *(float4*)&b2[0] = *(const float4*)&Bs[k][tx*4];
            *(float4*)&b2[4] = *(const float4*)&Bs[k][64 + tx*4];
#pragma unroll
            for (int i = 0; i < 8; i++)
#pragma unroll
                for (int j = 0; j < 8; j++)
                    acc[i][j] += a[i]*b2[j];
        }
        __syncthreads();
    }
#pragma unroll
    for (int i = 0; i < 8; i++) {
        int row = blockIdx.y*128 + ((i & 4) ? 64 : 0) + ty*4 + (i & 3);
        float* cp = C + (size_t)row*Emb + tx*4;
        *(float4*)cp        = make_float4(acc[i][0], acc[i][1], acc[i][2], acc[i][3]);
        *(float4*)(cp + 64) = make_float4(acc[i][4], acc[i][5], acc[i][6], acc[i][7]);
    }
}

// ---------------- host entry ----------------
extern "C" void kernel_launch(void* const* d_in, const int* in_sizes, int n_in,
                              void* d_out, int out_size) {
    const int*   idx    = (const int*)  d_in[0];
    const float* wte    = (const float*)d_in[1];
    const float* qkv_w  = (const float*)d_in[2];
    const float* attn_w = (const float*)d_in[3];
    const float* fc_w   = (const float*)d_in[4];
    const float* mlp_w  = (const float*)d_in[5];
    const float* n1_w   = (const float*)d_in[6];
    const float* n2_w   = (const float*)d_in[7];
    const float* lnf_w  = (const float*)d_in[8];
    const float* lm_w   = (const float*)d_in[9];
    float* out = (float*)d_out;
    (void)in_sizes; (void)n_in; (void)out_size;

    float *px, *pxn, *pqkv, *py, *ph, *ps;
    cudaGetSymbolAddress((void**)&px,   g_x);
    cudaGetSymbolAddress((void**)&pxn,  g_xn);
    cudaGetSymbolAddress((void**)&pqkv, g_qkv);
    cudaGetSymbolAddress((void**)&py,   g_y);
    cudaGetSymbolAddress((void**)&ph,   g_h);
    cudaGetSymbolAddress((void**)&ps,   g_s);

    cudaFuncSetAttribute(gemm_mma<0>, cudaFuncAttributeMaxDynamicSharedMemorySize, SM_TOTAL);
    cudaFuncSetAttribute(gemm_mma<1>, cudaFuncAttributeMaxDynamicSharedMemorySize, SM_TOTAL);
    cudaFuncSetAttribute(gemm_mma<2>, cudaFuncAttributeMaxDynamicSharedMemorySize, SM_TOTAL);

    embed_kernel<<<NTOK*Emb/4/256, 256>>>(idx, wte);

    for (int l = 0; l < NL; l++) {
        rmsnorm_kernel<<<NTOK, 256>>>(px, n1_w + (size_t)l*Emb, pxn);
        gemm_mma<0><<<dim3(NTOK/128, QKVD/128), 256, SM_TOTAL>>>(
            pxn, qkv_w + (size_t)l*QKVD*Emb, pqkv, nullptr, NTOK, QKVD, Emb);
        rope_kernel<<<NTOK*(NH+NG)*64/256, 256>>>();
        score_gemm<<<dim3(Tseq/128, Tseq/128, Bsz*NH), 256>>>(pqkv, ps);
        softmax_kernel<<<Bsz*NH*Tseq, 256>>>(ps);
        av_gemm<<<dim3(1, Tseq/128, Bsz*NH), 256>>>(ps, pqkv, py);
        gemm_mma<2><<<dim3(NTOK/128, Emb/128), 256, SM_TOTAL>>>(
            py, attn_w + (size_t)l*Emb*(NH*HSZ), px, px, NTOK, Emb, NH*HSZ);
        rmsnorm_kernel<<<NTOK, 256>>>(px, n2_w + (size_t)l*Emb, pxn);
        gemm_mma<1><<<dim3(NTOK/128, FFD/128), 256, SM_TOTAL>>>(
            pxn, fc_w + (size_t)l*FFD*Emb, ph, nullptr, NTOK, FFD, Emb);
        gemm_mma<2><<<dim3(NTOK/128, Emb/128), 256, SM_TOTAL>>>(
            ph, mlp_w + (size_t)l*Emb*FFD, px, px, NTOK, Emb, FFD);
    }

    rmsnorm_kernel<<<NTOK, 256>>>(px, lnf_w, pxn);
    gemm_mma<0><<<dim3(NTOK/128, Voc/128), 256, SM_TOTAL>>>(
        pxn, lm_w, out, nullptr, NTOK, Voc, Emb);
}